// round 5
// baseline (speedup 1.0000x reference)
#include <cuda_runtime.h>

#define CA_EPS  1e-8f
#define CA_K    512
#define CA_FF   16          // F*F
#define CA_HALF 8192        // K*FF : x-flat per batch / xc-half offset in W row
#define CA_FEAT 16384       // 2*K*FF : W row length
#define SLICE   16
#define NT      512
#define GRID    64

__device__ float    g_accum[4];   // zero at entry; restored to zero every call
__device__ unsigned g_count;      // zero at entry; restored to zero every call

// grid = 64 (32 slice-CTAs per batch), block = 512 (one thread per channel).
__global__ __launch_bounds__(NT, 1)
void ca_fused(const float* __restrict__ x, const float* __restrict__ W,
              const float* __restrict__ bias, float* __restrict__ out) {
    const int b    = blockIdx.x >> 5;            // batch (0..1)
    const int c0   = (blockIdx.x & 31) * SLICE;  // slice start channel
    const int tid  = threadIdx.x;
    const int lane = tid & 31, warp = tid >> 5;

    __shared__ float s_red[16];
    __shared__ float s_D[CA_K];
    __shared__ float s_fac[SLICE];

    // ---- early prefetch: bias (for the tail) -------------------------------
    float bias0 = 0.f, bias1 = 0.f;
    if (tid == 0) { bias0 = __ldg(bias); bias1 = __ldg(bias + 1); }

    // ---- prefetch matvec operands (threads 0..127) -------------------------
    float4 wa = make_float4(0.f, 0.f, 0.f, 0.f);
    float4 wb = wa, xu = wa;
    int ch_l = 0;
    if (tid < 128) {
        const int cls = tid >> 6;                // warps 0,1 -> class0; 2,3 -> class1
        const int u   = tid & 63;
        ch_l = u >> 2;
        const int v = u & 3;
        const float* wbase = W + (size_t)cls * CA_FEAT + (size_t)(c0 + ch_l) * CA_FF + v * 4;
        wa = *reinterpret_cast<const float4*>(wbase);
        wb = *reinterpret_cast<const float4*>(wbase + CA_HALF);
        xu = *reinterpret_cast<const float4*>(x + (size_t)b * CA_HALF + (size_t)(c0 + ch_l) * CA_FF + v * 4);
    }

    // ---- load own channel (k = tid): 4 contiguous float4 -------------------
    const float4* xp = reinterpret_cast<const float4*>(x + (size_t)b * CA_HALF) + (size_t)tid * 4;
    float4 a0 = xp[0], a1 = xp[1], a2 = xp[2], a3 = xp[3];

    // ---- phase 1: per-batch global max -------------------------------------
    float m = fmaxf(fmaxf(fmaxf(a0.x, a0.y), fmaxf(a0.z, a0.w)),
                    fmaxf(fmaxf(a1.x, a1.y), fmaxf(a1.z, a1.w)));
    m = fmaxf(m, fmaxf(fmaxf(fmaxf(a2.x, a2.y), fmaxf(a2.z, a2.w)),
                       fmaxf(fmaxf(a3.x, a3.y), fmaxf(a3.z, a3.w))));
    #pragma unroll
    for (int off = 16; off > 0; off >>= 1)
        m = fmaxf(m, __shfl_xor_sync(0xFFFFFFFFu, m, off));
    if (lane == 0) s_red[warp] = m;
    __syncthreads();
    float mm = s_red[0];
    #pragma unroll
    for (int i = 1; i < 16; ++i) mm = fmaxf(mm, s_red[i]);
    const float inv = 1.0f / (mm + CA_EPS);

    // ---- phase 2: lehmer_den D for the own channel -------------------------
    {
        float s1 = 0.f, s2 = 0.f, t;
        t = a0.x * inv + CA_EPS; s1 += t; s2 += t * t;
        t = a0.y * inv + CA_EPS; s1 += t; s2 += t * t;
        t = a0.z * inv + CA_EPS; s1 += t; s2 += t * t;
        t = a0.w * inv + CA_EPS; s1 += t; s2 += t * t;
        t = a1.x * inv + CA_EPS; s1 += t; s2 += t * t;
        t = a1.y * inv + CA_EPS; s1 += t; s2 += t * t;
        t = a1.z * inv + CA_EPS; s1 += t; s2 += t * t;
        t = a1.w * inv + CA_EPS; s1 += t; s2 += t * t;
        t = a2.x * inv + CA_EPS; s1 += t; s2 += t * t;
        t = a2.y * inv + CA_EPS; s1 += t; s2 += t * t;
        t = a2.z * inv + CA_EPS; s1 += t; s2 += t * t;
        t = a2.w * inv + CA_EPS; s1 += t; s2 += t * t;
        t = a3.x * inv + CA_EPS; s1 += t; s2 += t * t;
        t = a3.y * inv + CA_EPS; s1 += t; s2 += t * t;
        t = a3.z * inv + CA_EPS; s1 += t; s2 += t * t;
        t = a3.w * inv + CA_EPS; s1 += t; s2 += t * t;
        s_D[tid] = (s2 + CA_EPS) / (s1 + CA_EPS) + CA_EPS;
    }
    __syncthreads();

    // ---- phase 3: pairwise compares, warp w handles slice channel c0+w -----
    // bool[m,n] decision reduces to sign(D[m]-D[n]); fac = relu(wins-losses).
    {
        const float Dk = s_D[c0 + warp];        // broadcast (all lanes same addr)
        int wl = 0;
        #pragma unroll
        for (int i = 0; i < 16; ++i) {          // conflict-free: stride-1 by lane
            float d = s_D[i * 32 + lane];
            wl += (Dk > d) - (d > Dk);
        }
        #pragma unroll
        for (int off = 16; off > 0; off >>= 1)
            wl += __shfl_xor_sync(0xFFFFFFFFu, wl, off);
        if (lane == 0) s_fac[warp] = fmaxf((float)wl, 0.0f);
    }
    __syncthreads();

    // ---- phase 4: slice matvec partial -> global RED -----------------------
    if (warp < 4) {
        const float f = s_fac[ch_l];
        float part;
        part  = xu.x * fmaf(f, wb.x, wa.x);
        part += xu.y * fmaf(f, wb.y, wa.y);
        part += xu.z * fmaf(f, wb.z, wa.z);
        part += xu.w * fmaf(f, wb.w, wa.w);
        #pragma unroll
        for (int off = 16; off > 0; off >>= 1)
            part += __shfl_xor_sync(0xFFFFFFFFu, part, off);
        if (lane == 0) atomicAdd(&g_accum[b * 2 + (warp >> 1)], part);
    }
    __syncthreads();

    // ---- last-CTA finalize (restores scratch to zero for next call) --------
    if (tid == 0) {
        __threadfence();                          // REDs visible before ticket
        unsigned ticket = atomicAdd(&g_count, 1u);
        if (ticket == GRID - 1) {
            // all 64 tickets in => all REDs visible at L2; plain L2 reads OK
            float r0 = __ldcg(&g_accum[0]);
            float r1 = __ldcg(&g_accum[1]);
            float r2 = __ldcg(&g_accum[2]);
            float r3 = __ldcg(&g_accum[3]);
            float4 res = make_float4(bias0 + r0, bias1 + r1, bias0 + r2, bias1 + r3);
            *reinterpret_cast<float4*>(out) = res;
            __stcg(&g_accum[0], 0.0f);
            __stcg(&g_accum[1], 0.0f);
            __stcg(&g_accum[2], 0.0f);
            __stcg(&g_accum[3], 0.0f);
            __stcg(&g_count, 0u);
        }
    }
}

extern "C" void kernel_launch(void* const* d_in, const int* in_sizes, int n_in,
                              void* d_out, int out_size) {
    const float* x    = (const float*)d_in[0];   // [2, 512, 4, 4]
    const float* W    = (const float*)d_in[1];   // [2, 16384]
    const float* bias = (const float*)d_in[2];   // [2]
    float* out = (float*)d_out;                  // [2, 2]
    ca_fused<<<GRID, NT>>>(x, W, bias, out);
}